// round 8
// baseline (speedup 1.0000x reference)
#include <cuda_runtime.h>
#include <cuda_bf16.h>

// Problem constants
#define NUM_CW   512
#define CDIM     64
#define CHUNK_K  128            // codewords resident in smem per chunk
#define N_CHUNKS (NUM_CW / CHUNK_K)
#define N_IMG    32
#define HWSZ     4096           // 64*64
#define T_TOK    (N_IMG * HWSZ) // 131072 tokens
#define GAMMA_F  0.99f
#define TN       4              // codewords per inner group (indep. acc chains)
#define TM       2              // tokens per thread

// Output layout: q | codebook_new | N_new | m_new
#define OFF_Q   0
#define OFF_CB  (N_IMG * CDIM * HWSZ)          // 8388608
#define OFF_N   (OFF_CB + NUM_CW * CDIM)       // 8421376
#define OFF_M   (OFF_N + NUM_CW)               // 8421888

// Scratch (device globals; zeroed at load, re-zeroed by finalize each call)
__device__ float g_counts[NUM_CW];
__device__ float g_sums[NUM_CW * CDIM];
__device__ float g_cnorm[NUM_CW];

#define FMA_F32X2(acc, a, b) \
    asm("fma.rn.f32x2 %0, %1, %2, %0;" : "+l"(acc) : "l"(a), "l"(b))
#define PACK2(out, lo, hi) \
    asm("mov.b64 %0, {%1, %2};" : "=l"(out) : "f"(lo), "f"(hi))
#define UNPACK2(lo, hi, in) \
    asm("mov.b64 {%0, %1}, %2;" : "=f"(lo), "=f"(hi) : "l"(in))

// Coalesced norm computation: thread i squares codebook[i]; warp-shuffle
// reduces each 32-lane half-row; lane 0 atomically combines into g_cnorm.
__global__ void init_kernel(const float* __restrict__ codebook) {
    int i = blockIdx.x * blockDim.x + threadIdx.x;  // 0 .. 32767
    float v = codebook[i];
    float s = v * v;
#pragma unroll
    for (int off = 16; off > 0; off >>= 1)
        s += __shfl_down_sync(0xFFFFFFFFu, s, off);
    if ((threadIdx.x & 31) == 0)
        atomicAdd(&g_cnorm[i >> 6], s);
}

// Each thread owns TM=2 tokens (tid and tid+128 within a 256-token block).
// 4 CTAs/SM resident (full register file: 4*128 thr * 128 regs = 64k regs),
// giving 4 warps/SMSP to hide the LDS->FFMA2 latency heads.
__global__ __launch_bounds__(128, 4)
void assign_kernel(const float* __restrict__ x,
                   const float* __restrict__ codebook,
                   float* __restrict__ out) {
    __shared__ float scb[CHUNK_K * CDIM];   // 32 KB
    __shared__ float snorm[CHUNK_K];

    const int tid = threadIdx.x;
    const int t0  = blockIdx.x * 256 + tid;      // token A
    const int t1  = t0 + 128;                    // token B (same image n)
    const int n   = t0 >> 12;
    const int hw0 = t0 & (HWSZ - 1);
    const int hw1 = t1 & (HWSZ - 1);
    const int base0 = n * (CDIM * HWSZ) + hw0;
    const int base1 = n * (CDIM * HWSZ) + hw1;

    // x features for both tokens, packed as f32x2 (channels 2i, 2i+1)
    unsigned long long xa[CDIM / 2], xb[CDIM / 2];
#pragma unroll
    for (int i = 0; i < CDIM / 2; i++) {
        float a0 = x[base0 + (2 * i) * HWSZ];
        float a1 = x[base0 + (2 * i + 1) * HWSZ];
        PACK2(xa[i], a0, a1);
        float b0 = x[base1 + (2 * i) * HWSZ];
        float b1 = x[base1 + (2 * i + 1) * HWSZ];
        PACK2(xb[i], b0, b1);
    }

    float best_da = 3.4e38f, best_db = 3.4e38f;
    int   best_ka = 0,       best_kb = 0;

    for (int ch = 0; ch < N_CHUNKS; ch++) {
        __syncthreads();
        {
            const float4* src = (const float4*)(codebook + ch * CHUNK_K * CDIM);
            float4* dst = (float4*)scb;
#pragma unroll
            for (int i = 0; i < (CHUNK_K * CDIM / 4) / 128; i++)
                dst[tid + i * 128] = src[tid + i * 128];
            snorm[tid] = g_cnorm[ch * CHUNK_K + tid];
        }
        __syncthreads();

        const ulonglong2* cb2 = (const ulonglong2*)scb;  // 16 per codeword row
#pragma unroll 1
        for (int g = 0; g < CHUNK_K / TN; g++) {
            unsigned long long acca[TN], accb[TN];
#pragma unroll
            for (int j = 0; j < TN; j++) { acca[j] = 0ULL; accb[j] = 0ULL; }

            const ulonglong2* r0 = cb2 + (g * TN) * (CDIM / 4);
#pragma unroll
            for (int i = 0; i < CDIM / 4; i++) {
#pragma unroll
                for (int j = 0; j < TN; j++) {
                    ulonglong2 v = r0[j * (CDIM / 4) + i];  // broadcast LDS.128
                    FMA_F32X2(acca[j], xa[2 * i],     v.x);
                    FMA_F32X2(acca[j], xa[2 * i + 1], v.y);
                    FMA_F32X2(accb[j], xb[2 * i],     v.x);
                    FMA_F32X2(accb[j], xb[2 * i + 1], v.y);
                }
            }
#pragma unroll
            for (int j = 0; j < TN; j++) {
                int k = ch * CHUNK_K + g * TN + j;
                float nrm = snorm[g * TN + j];
                float lo, hi;
                UNPACK2(lo, hi, acca[j]);
                float da = fmaf(-2.0f, lo + hi, nrm);
                if (da < best_da) { best_da = da; best_ka = k; }
                UNPACK2(lo, hi, accb[j]);
                float db = fmaf(-2.0f, lo + hi, nrm);
                if (db < best_db) { best_db = db; best_kb = k; }
            }
        }
    }

    // Write q for both tokens (strided layout, coalesced across the warp)
    const float4* cwa = (const float4*)(codebook + best_ka * CDIM);
    const float4* cwb = (const float4*)(codebook + best_kb * CDIM);
#pragma unroll
    for (int i = 0; i < CDIM / 4; i++) {
        float4 va = cwa[i];
        out[OFF_Q + base0 + (4 * i + 0) * HWSZ] = va.x;
        out[OFF_Q + base0 + (4 * i + 1) * HWSZ] = va.y;
        out[OFF_Q + base0 + (4 * i + 2) * HWSZ] = va.z;
        out[OFF_Q + base0 + (4 * i + 3) * HWSZ] = va.w;
        float4 vb = cwb[i];
        out[OFF_Q + base1 + (4 * i + 0) * HWSZ] = vb.x;
        out[OFF_Q + base1 + (4 * i + 1) * HWSZ] = vb.y;
        out[OFF_Q + base1 + (4 * i + 2) * HWSZ] = vb.z;
        out[OFF_Q + base1 + (4 * i + 3) * HWSZ] = vb.w;
    }

    // EMA stats
    atomicAdd(&g_counts[best_ka], 1.0f);
    atomicAdd(&g_counts[best_kb], 1.0f);
    float* sa = &g_sums[best_ka * CDIM];
    float* sb = &g_sums[best_kb * CDIM];
#pragma unroll
    for (int i = 0; i < CDIM / 2; i++) {
        float u, v;
        UNPACK2(u, v, xa[i]);
        atomicAdd(&sa[2 * i],     u);
        atomicAdd(&sa[2 * i + 1], v);
        UNPACK2(u, v, xb[i]);
        atomicAdd(&sb[2 * i],     u);
        atomicAdd(&sb[2 * i + 1], v);
    }
}

// One thread per (k, c). Also resets scratch for the next call.
__global__ void finalize_kernel(const float* __restrict__ N_state,
                                const float* __restrict__ m_state,
                                float* __restrict__ out) {
    int i = blockIdx.x * blockDim.x + threadIdx.x;
    if (i >= NUM_CW * CDIM) return;
    int k = i / CDIM;
    float cnt = g_counts[k];
    bool occ = cnt > 0.0f;
    float Nold = N_state[k];
    float Nn = occ ? (Nold * GAMMA_F + cnt * (1.0f - GAMMA_F)) : Nold;
    float mold = m_state[i];
    float mn = occ ? (mold * GAMMA_F + g_sums[i] * (1.0f - GAMMA_F)) : mold;
    out[OFF_M + i]  = mn;
    out[OFF_CB + i] = mn / Nn;
    g_sums[i] = 0.0f;
    if ((i % CDIM) == 0) out[OFF_N + k] = Nn;
    if (i < NUM_CW) { g_counts[i] = 0.0f; g_cnorm[i] = 0.0f; }
}

extern "C" void kernel_launch(void* const* d_in, const int* in_sizes, int n_in,
                              void* d_out, int out_size) {
    const float* x        = (const float*)d_in[0];
    const float* codebook = (const float*)d_in[1];
    const float* N_state  = (const float*)d_in[2];
    const float* m_state  = (const float*)d_in[3];
    float* out = (float*)d_out;

    init_kernel<<<NUM_CW * CDIM / 256, 256>>>(codebook);
    assign_kernel<<<T_TOK / 256, 128>>>(x, codebook, out);
    finalize_kernel<<<(NUM_CW * CDIM + 255) / 256, 256>>>(N_state, m_state, out);
}

// round 9
// speedup vs baseline: 2.1222x; 2.1222x over previous
#include <cuda_runtime.h>
#include <cuda_bf16.h>

// Problem constants
#define NUM_CW   512
#define CDIM     64
#define N_IMG    32
#define HWSZ     4096            // 64*64
#define T_TOK    (N_IMG * HWSZ)  // 131072 tokens
#define GAMMA_F  0.99f

// Tiling
#define BM       128             // tokens per block
#define BN       32              // codewords per chunk
#define N_CHUNK  (NUM_CW / BN)   // 16
#define TM       8               // tokens per thread (4 f32x2 pairs)
#define TN       4               // codewords per thread
#define NTHR     128             // (BM/TM)*(BN/TN) = 16*8
#define CS_PAD   40              // row stride for cs (160B, 16B-aligned)

// Output layout: q | codebook_new | N_new | m_new
#define OFF_Q   0
#define OFF_CB  (N_IMG * CDIM * HWSZ)          // 8388608
#define OFF_N   (OFF_CB + NUM_CW * CDIM)       // 8421376
#define OFF_M   (OFF_N + NUM_CW)               // 8421888

// Scratch (device globals; zeroed at load, re-zeroed by finalize each call)
__device__ float g_counts[NUM_CW];
__device__ float g_sums[NUM_CW * CDIM];
__device__ float g_cnorm[NUM_CW];
__device__ float g_cbT[CDIM * NUM_CW];   // codebook transposed: [c][k]

#define FMA_F32X2(acc, a, b) \
    asm("fma.rn.f32x2 %0, %1, %2, %0;" : "+l"(acc) : "l"(a), "l"(b))
#define PACK2(out, lo, hi) \
    asm("mov.b64 %0, {%1, %2};" : "=l"(out) : "f"(lo), "f"(hi))
#define UNPACK2(lo, hi, in) \
    asm("mov.b64 {%0, %1}, %2;" : "=f"(lo), "=f"(hi) : "l"(in))

// Norms (warp-shuffle + atomic) and codebook transpose.
__global__ void init_kernel(const float* __restrict__ codebook) {
    int i = blockIdx.x * blockDim.x + threadIdx.x;  // 0 .. 32767
    float v = codebook[i];
    int k = i >> 6, c = i & 63;
    g_cbT[c * NUM_CW + k] = v;
    float s = v * v;
#pragma unroll
    for (int off = 16; off > 0; off >>= 1)
        s += __shfl_down_sync(0xFFFFFFFFu, s, off);
    if ((threadIdx.x & 31) == 0)
        atomicAdd(&g_cnorm[k], s);
}

// SGEMM-style: x tile and codebook chunk both in smem; registers hold only
// the 4x4 f32x2 accumulator tile. 5 CTAs/SM resident.
__global__ __launch_bounds__(NTHR)
void assign_kernel(const float* __restrict__ x,
                   const float* __restrict__ codebook,
                   float* __restrict__ out) {
    __shared__ __align__(16) float xs[CDIM][BM];      // 32 KB, [c][token]
    __shared__ __align__(16) float cs[CDIM][CS_PAD];  // 10 KB, [c][k-in-chunk]
    __shared__ float snorm[NUM_CW];                   // 2 KB

    const int tid = threadIdx.x;
    const int tx  = tid & 7;          // codeword group 0..7
    const int ty  = tid >> 3;         // token group 0..15
    const int t0  = blockIdx.x * BM;  // first token of block
    const int n   = t0 >> 12;
    const int hw0 = t0 & (HWSZ - 1);
    const long base = (long)n * (CDIM * HWSZ) + hw0;

    // Load x tile: 64 rows of 128 floats, each row contiguous in gmem.
    {
        const float* xsrc = x + base;
#pragma unroll
        for (int i = 0; i < (CDIM * BM / 4) / NTHR; i++) {   // 16 iters
            int idx = tid + i * NTHR;       // 0..2047 float4 slots
            int c = idx >> 5, q4 = idx & 31;
            float4 v = *(const float4*)(xsrc + c * HWSZ + q4 * 4);
            *(float4*)&xs[c][q4 * 4] = v;
        }
#pragma unroll
        for (int i = 0; i < NUM_CW / NTHR; i++)
            snorm[tid + i * NTHR] = g_cnorm[tid + i * NTHR];
    }

    float best_d[TM];
    int   best_k[TM];
#pragma unroll
    for (int m = 0; m < TM; m++) { best_d[m] = 3.4e38f; best_k[m] = 0; }

    for (int ch = 0; ch < N_CHUNK; ch++) {
        __syncthreads();
        // Load codebook chunk (c-major) from pre-transposed g_cbT.
#pragma unroll
        for (int i = 0; i < (CDIM * BN / 4) / NTHR; i++) {   // 4 iters
            int idx = tid + i * NTHR;       // 0..511 float4 slots
            int c = idx >> 3, j = idx & 7;
            float4 v = *(const float4*)(g_cbT + c * NUM_CW + ch * BN + j * 4);
            *(float4*)&cs[c][j * 4] = v;
        }
        __syncthreads();

        unsigned long long acc[TM / 2][TN];
#pragma unroll
        for (int p = 0; p < TM / 2; p++)
#pragma unroll
            for (int j = 0; j < TN; j++) acc[p][j] = 0ULL;

#pragma unroll 4
        for (int c = 0; c < CDIM; c++) {
            const ulonglong2* xrow = (const ulonglong2*)&xs[c][ty * TM];
            ulonglong2 xA = xrow[0];   // token pairs (0,1),(2,3)
            ulonglong2 xB = xrow[1];   // token pairs (4,5),(6,7)
            float4 cv = *(const float4*)&cs[c][tx * TN];
            unsigned long long c0, c1, c2, c3;
            PACK2(c0, cv.x, cv.x);
            PACK2(c1, cv.y, cv.y);
            PACK2(c2, cv.z, cv.z);
            PACK2(c3, cv.w, cv.w);
            FMA_F32X2(acc[0][0], xA.x, c0);
            FMA_F32X2(acc[0][1], xA.x, c1);
            FMA_F32X2(acc[0][2], xA.x, c2);
            FMA_F32X2(acc[0][3], xA.x, c3);
            FMA_F32X2(acc[1][0], xA.y, c0);
            FMA_F32X2(acc[1][1], xA.y, c1);
            FMA_F32X2(acc[1][2], xA.y, c2);
            FMA_F32X2(acc[1][3], xA.y, c3);
            FMA_F32X2(acc[2][0], xB.x, c0);
            FMA_F32X2(acc[2][1], xB.x, c1);
            FMA_F32X2(acc[2][2], xB.x, c2);
            FMA_F32X2(acc[2][3], xB.x, c3);
            FMA_F32X2(acc[3][0], xB.y, c0);
            FMA_F32X2(acc[3][1], xB.y, c1);
            FMA_F32X2(acc[3][2], xB.y, c2);
            FMA_F32X2(acc[3][3], xB.y, c3);
        }

        // Update per-token argmin over this chunk's TN codewords.
        int k0 = ch * BN + tx * TN;
#pragma unroll
        for (int j = 0; j < TN; j++) {
            float nrm = snorm[k0 + j];
#pragma unroll
            for (int p = 0; p < TM / 2; p++) {
                float lo, hi;
                UNPACK2(lo, hi, acc[p][j]);
                float d0 = fmaf(-2.0f, lo, nrm);
                float d1 = fmaf(-2.0f, hi, nrm);
                if (d0 < best_d[2 * p])     { best_d[2 * p] = d0;     best_k[2 * p] = k0 + j; }
                if (d1 < best_d[2 * p + 1]) { best_d[2 * p + 1] = d1; best_k[2 * p + 1] = k0 + j; }
            }
        }
    }

    // Cross-tx argmin reduction via packed keys in smem (alias cs).
    __syncthreads();
    unsigned long long* sred = (unsigned long long*)cs;  // [BM][8]
#pragma unroll
    for (int m = 0; m < TM; m++) {
        unsigned int u = __float_as_uint(best_d[m]);
        u = (u & 0x80000000u) ? ~u : (u | 0x80000000u);   // order-preserving
        sred[(ty * TM + m) * 8 + tx] =
            ((unsigned long long)u << 32) | (unsigned int)best_k[m];
    }
    __syncthreads();

    // One thread per token: finish argmin, write q, EMA atomics.
    {
        const int tok = tid;   // 0..127
        unsigned long long best = sred[tok * 8];
#pragma unroll
        for (int i = 1; i < 8; i++) {
            unsigned long long v = sred[tok * 8 + i];
            if (v < best) best = v;
        }
        int bk = (int)(best & 0xFFFFFFFFu);

        atomicAdd(&g_counts[bk], 1.0f);
        const float4* cw4 = (const float4*)(codebook + bk * CDIM);
        float* qo = out + OFF_Q + base + tok;
        float* sums = &g_sums[bk * CDIM];
#pragma unroll
        for (int i = 0; i < CDIM / 4; i++) {
            float4 v = cw4[i];
            qo[(4 * i + 0) * HWSZ] = v.x;
            qo[(4 * i + 1) * HWSZ] = v.y;
            qo[(4 * i + 2) * HWSZ] = v.z;
            qo[(4 * i + 3) * HWSZ] = v.w;
        }
#pragma unroll
        for (int c = 0; c < CDIM; c++)
            atomicAdd(&sums[c], xs[c][tok]);
    }
}

// One thread per (k, c). Also resets scratch for the next call.
__global__ void finalize_kernel(const float* __restrict__ N_state,
                                const float* __restrict__ m_state,
                                float* __restrict__ out) {
    int i = blockIdx.x * blockDim.x + threadIdx.x;
    if (i >= NUM_CW * CDIM) return;
    int k = i / CDIM;
    float cnt = g_counts[k];
    bool occ = cnt > 0.0f;
    float Nold = N_state[k];
    float Nn = occ ? (Nold * GAMMA_F + cnt * (1.0f - GAMMA_F)) : Nold;
    float mold = m_state[i];
    float mn = occ ? (mold * GAMMA_F + g_sums[i] * (1.0f - GAMMA_F)) : mold;
    out[OFF_M + i]  = mn;
    out[OFF_CB + i] = mn / Nn;
    g_sums[i] = 0.0f;
    if ((i % CDIM) == 0) out[OFF_N + k] = Nn;
    if (i < NUM_CW) { g_counts[i] = 0.0f; g_cnorm[i] = 0.0f; }
}

extern "C" void kernel_launch(void* const* d_in, const int* in_sizes, int n_in,
                              void* d_out, int out_size) {
    const float* x        = (const float*)d_in[0];
    const float* codebook = (const float*)d_in[1];
    const float* N_state  = (const float*)d_in[2];
    const float* m_state  = (const float*)d_in[3];
    float* out = (float*)d_out;

    init_kernel<<<NUM_CW * CDIM / 256, 256>>>(codebook);
    assign_kernel<<<T_TOK / BM, NTHR>>>(x, codebook, out);
    finalize_kernel<<<(NUM_CW * CDIM + 255) / 256, 256>>>(N_state, m_state, out);
}